// round 4
// baseline (speedup 1.0000x reference)
#include <cuda_runtime.h>

// ---------------- problem-size capacities (fixed by the dataset) -------------
#define MAXN 50000
#define MAXE 800000
#define MAXET (MAXN + MAXE)

// ---------------- device scratch (no allocation allowed) ---------------------
__device__ float g_h1[MAXN * 128];     // x @ W1
__device__ float g_h2[MAXN * 128];     // elu(layer1 out)
__device__ float g_hmu[MAXN * 32];     // h2 @ Wmu
__device__ float g_hlv[MAXN * 32];     // h2 @ Wlv
__device__ float g_asrc1[MAXN * 2];    // per-node att dots, layer1 (2 heads)
__device__ float g_adst1[MAXN * 2];
__device__ float2 g_a2s[MAXN];         // {a_src_mu, a_src_lv}
__device__ float2 g_a2d[MAXN];         // {a_dst_mu, a_dst_lv}
__device__ int   g_counts[MAXN];
__device__ int   g_row[MAXN + 1];
__device__ int   g_cursor[MAXN];
__device__ int   g_srcs[MAXET];        // CSR (by dst) of source node ids

// ---------------- CSR build --------------------------------------------------
__global__ void zero_counts_kernel(int n) {
    int i = blockIdx.x * blockDim.x + threadIdx.x;
    if (i < n) g_counts[i] = 0;
}

__global__ void hist_kernel(const int* __restrict__ ei, int E, int N) {
    int e = blockIdx.x * blockDim.x + threadIdx.x;
    int ET = E + N;
    if (e >= ET) return;
    int dst = (e < E) ? ei[E + e] : (e - E);   // self-loop tail
    atomicAdd(&g_counts[dst], 1);
}

__global__ void scan_kernel(int n, int total) {
    __shared__ int sdata[1024];
    __shared__ int carry;
    int tid = threadIdx.x;
    if (tid == 0) carry = 0;
    __syncthreads();
    for (int base = 0; base < n; base += 1024) {
        int i = base + tid;
        int v = (i < n) ? g_counts[i] : 0;
        sdata[tid] = v;
        __syncthreads();
        // Hillis-Steele inclusive scan
        for (int off = 1; off < 1024; off <<= 1) {
            int t2 = (tid >= off) ? sdata[tid - off] : 0;
            __syncthreads();
            sdata[tid] += t2;
            __syncthreads();
        }
        int excl = sdata[tid] - v + carry;
        if (i < n) { g_row[i] = excl; g_cursor[i] = excl; }
        __syncthreads();
        if (tid == 0) carry += sdata[1023];
        __syncthreads();
    }
    if (tid == 0) g_row[n] = total;
}

__global__ void scatter_kernel(const int* __restrict__ ei, int E, int N) {
    int e = blockIdx.x * blockDim.x + threadIdx.x;
    int ET = E + N;
    if (e >= ET) return;
    int src, dst;
    if (e < E) { src = ei[e]; dst = ei[E + e]; }
    else       { src = e - E; dst = e - E; }
    int pos = atomicAdd(&g_cursor[dst], 1);
    g_srcs[pos] = src;
}

// ---------------- GEMM: C[M,BN] = A[M,128] @ B[128,BN] ----------------------
template <int BN>
__global__ void gemm_k128(const float* __restrict__ A, const float* __restrict__ B,
                          float* __restrict__ C, int M) {
    constexpr int BM = 64, BK = 32;
    constexpr int TX = BN / 4;        // threads along cols (each does 4 cols)
    constexpr int TY = 256 / TX;      // threads along rows
    constexpr int RPT = BM / TY;      // rows per thread
    __shared__ float As[BK][BM + 1];
    __shared__ float Bs[BK][BN];
    int t = threadIdx.x;
    int tx = t % TX, ty = t / TX;
    int row0 = blockIdx.x * BM;
    float acc[RPT][4];
#pragma unroll
    for (int r = 0; r < RPT; r++) { acc[r][0] = acc[r][1] = acc[r][2] = acc[r][3] = 0.f; }

    for (int k0 = 0; k0 < 128; k0 += BK) {
        for (int i = t; i < BM * BK; i += 256) {
            int r = i / BK, kk = i % BK;
            int gr = row0 + r;
            As[kk][r] = (gr < M) ? A[gr * 128 + k0 + kk] : 0.f;
        }
        for (int i = t; i < BK * BN; i += 256) {
            int kk = i / BN, c = i % BN;
            Bs[kk][c] = B[(k0 + kk) * BN + c];
        }
        __syncthreads();
#pragma unroll
        for (int kk = 0; kk < BK; kk++) {
            float4 bv = *(const float4*)&Bs[kk][tx * 4];
#pragma unroll
            for (int r = 0; r < RPT; r++) {
                float a = As[kk][ty * RPT + r];
                acc[r][0] = fmaf(a, bv.x, acc[r][0]);
                acc[r][1] = fmaf(a, bv.y, acc[r][1]);
                acc[r][2] = fmaf(a, bv.z, acc[r][2]);
                acc[r][3] = fmaf(a, bv.w, acc[r][3]);
            }
        }
        __syncthreads();
    }
#pragma unroll
    for (int r = 0; r < RPT; r++) {
        int gr = row0 + ty * RPT + r;
        if (gr < M) {
            float4 v = make_float4(acc[r][0], acc[r][1], acc[r][2], acc[r][3]);
            *(float4*)&C[gr * BN + tx * 4] = v;
        }
    }
}

// ---------------- per-node attention dots, layer 1 ---------------------------
__global__ void attdot1_kernel(const float* __restrict__ att_src,
                               const float* __restrict__ att_dst, int N) {
    int gid = blockIdx.x * blockDim.x + threadIdx.x;
    int n = gid >> 5, lane = gid & 31;
    if (n >= N) return;
    float4 hv = *(const float4*)&g_h1[n * 128 + lane * 4];
    float4 as = *(const float4*)&att_src[lane * 4];
    float4 av = *(const float4*)&att_dst[lane * 4];
    float ds = hv.x * as.x + hv.y * as.y + hv.z * as.z + hv.w * as.w;
    float dd = hv.x * av.x + hv.y * av.y + hv.z * av.z + hv.w * av.w;
#pragma unroll
    for (int off = 8; off; off >>= 1) {   // reduce within 16-lane half (per head)
        ds += __shfl_xor_sync(0xffffffffu, ds, off);
        dd += __shfl_xor_sync(0xffffffffu, dd, off);
    }
    if ((lane & 15) == 0) {
        g_asrc1[n * 2 + (lane >> 4)] = ds;
        g_adst1[n * 2 + (lane >> 4)] = dd;
    }
}

// ---------------- layer-1 softmax + aggregation + bias + ELU -----------------
__global__ void agg1_kernel(const float* __restrict__ b1, int N) {
    int gid = blockIdx.x * blockDim.x + threadIdx.x;
    int n = gid >> 5, lane = gid & 31;
    if (n >= N) return;
    int start = g_row[n], end = g_row[n + 1];
    float2 ad = *(const float2*)&g_adst1[2 * n];

    // pass 1: per-head max logit (lane-strided)
    float m0 = -1e30f, m1 = -1e30f;
    for (int i = start + lane; i < end; i += 32) {
        int s = g_srcs[i];
        float2 a = *(const float2*)&g_asrc1[2 * s];
        float l0 = a.x + ad.x; l0 = l0 > 0.f ? l0 : 0.2f * l0;
        float l1 = a.y + ad.y; l1 = l1 > 0.f ? l1 : 0.2f * l1;
        m0 = fmaxf(m0, l0); m1 = fmaxf(m1, l1);
    }
#pragma unroll
    for (int off = 16; off; off >>= 1) {
        m0 = fmaxf(m0, __shfl_xor_sync(0xffffffffu, m0, off));
        m1 = fmaxf(m1, __shfl_xor_sync(0xffffffffu, m1, off));
    }

    // pass 2: whole warp per edge; lane owns 4 channels (head = lane>=16)
    float a0 = 0.f, a1 = 0.f, a2 = 0.f, a3 = 0.f, s0 = 0.f, s1 = 0.f;
    int cb = lane * 4;
    bool head1 = lane >= 16;
    int i = start;
    for (; i + 1 < end; i += 2) {
        int sa = g_srcs[i], sb = g_srcs[i + 1];
        float2 ea = *(const float2*)&g_asrc1[2 * sa];
        float2 eb = *(const float2*)&g_asrc1[2 * sb];
        float4 ha = *(const float4*)&g_h1[sa * 128 + cb];
        float4 hb = *(const float4*)&g_h1[sb * 128 + cb];
        float la0 = ea.x + ad.x; la0 = la0 > 0.f ? la0 : 0.2f * la0; float wa0 = __expf(la0 - m0);
        float la1 = ea.y + ad.y; la1 = la1 > 0.f ? la1 : 0.2f * la1; float wa1 = __expf(la1 - m1);
        float lb0 = eb.x + ad.x; lb0 = lb0 > 0.f ? lb0 : 0.2f * lb0; float wb0 = __expf(lb0 - m0);
        float lb1 = eb.y + ad.y; lb1 = lb1 > 0.f ? lb1 : 0.2f * lb1; float wb1 = __expf(lb1 - m1);
        s0 += wa0 + wb0; s1 += wa1 + wb1;
        float wa = head1 ? wa1 : wa0;
        float wb = head1 ? wb1 : wb0;
        a0 = fmaf(wa, ha.x, fmaf(wb, hb.x, a0));
        a1 = fmaf(wa, ha.y, fmaf(wb, hb.y, a1));
        a2 = fmaf(wa, ha.z, fmaf(wb, hb.z, a2));
        a3 = fmaf(wa, ha.w, fmaf(wb, hb.w, a3));
    }
    if (i < end) {
        int sa = g_srcs[i];
        float2 ea = *(const float2*)&g_asrc1[2 * sa];
        float4 ha = *(const float4*)&g_h1[sa * 128 + cb];
        float la0 = ea.x + ad.x; la0 = la0 > 0.f ? la0 : 0.2f * la0; float wa0 = __expf(la0 - m0);
        float la1 = ea.y + ad.y; la1 = la1 > 0.f ? la1 : 0.2f * la1; float wa1 = __expf(la1 - m1);
        s0 += wa0; s1 += wa1;
        float wa = head1 ? wa1 : wa0;
        a0 = fmaf(wa, ha.x, a0); a1 = fmaf(wa, ha.y, a1);
        a2 = fmaf(wa, ha.z, a2); a3 = fmaf(wa, ha.w, a3);
    }
    float inv = 1.f / ((head1 ? s1 : s0) + 1e-16f);
    float4 bb = *(const float4*)&b1[cb];
    float o0 = a0 * inv + bb.x; o0 = o0 > 0.f ? o0 : __expf(o0) - 1.f;
    float o1 = a1 * inv + bb.y; o1 = o1 > 0.f ? o1 : __expf(o1) - 1.f;
    float o2 = a2 * inv + bb.z; o2 = o2 > 0.f ? o2 : __expf(o2) - 1.f;
    float o3 = a3 * inv + bb.w; o3 = o3 > 0.f ? o3 : __expf(o3) - 1.f;
    *(float4*)&g_h2[n * 128 + cb] = make_float4(o0, o1, o2, o3);
}

// ---------------- per-node attention dots, mu + lv (fused) -------------------
__global__ void attdot2_kernel(const float* __restrict__ asmu, const float* __restrict__ admu,
                               const float* __restrict__ aslv, const float* __restrict__ adlv,
                               int N) {
    int gid = blockIdx.x * blockDim.x + threadIdx.x;
    int n = gid >> 5, lane = gid & 31;
    if (n >= N) return;
    float vmu = g_hmu[n * 32 + lane];
    float vlv = g_hlv[n * 32 + lane];
    float s1 = vmu * asmu[lane], d1 = vmu * admu[lane];
    float s2 = vlv * aslv[lane], d2 = vlv * adlv[lane];
#pragma unroll
    for (int off = 16; off; off >>= 1) {
        s1 += __shfl_xor_sync(0xffffffffu, s1, off);
        d1 += __shfl_xor_sync(0xffffffffu, d1, off);
        s2 += __shfl_xor_sync(0xffffffffu, s2, off);
        d2 += __shfl_xor_sync(0xffffffffu, d2, off);
    }
    if (lane == 0) {
        g_a2s[n] = make_float2(s1, s2);
        g_a2d[n] = make_float2(d1, d2);
    }
}

// ---------------- mu + lv softmax + aggregation (fused), writes output -------
__global__ void agg2_kernel(const float* __restrict__ bmu, const float* __restrict__ blv,
                            float* __restrict__ out, int N) {
    int gid = blockIdx.x * blockDim.x + threadIdx.x;
    int n = gid >> 5, lane = gid & 31;
    if (n >= N) return;
    int start = g_row[n], end = g_row[n + 1];
    float2 ad = g_a2d[n];

    float mmu = -1e30f, mlv = -1e30f;
    for (int i = start + lane; i < end; i += 32) {
        int s = g_srcs[i];
        float2 a = g_a2s[s];
        float l = a.x + ad.x; l = l > 0.f ? l : 0.2f * l; mmu = fmaxf(mmu, l);
        float l2 = a.y + ad.y; l2 = l2 > 0.f ? l2 : 0.2f * l2; mlv = fmaxf(mlv, l2);
    }
#pragma unroll
    for (int off = 16; off; off >>= 1) {
        mmu = fmaxf(mmu, __shfl_xor_sync(0xffffffffu, mmu, off));
        mlv = fmaxf(mlv, __shfl_xor_sync(0xffffffffu, mlv, off));
    }

    float accm = 0.f, accl = 0.f, sm = 0.f, sl = 0.f;
    int i = start;
    for (; i + 1 < end; i += 2) {
        int sa = g_srcs[i], sb = g_srcs[i + 1];
        float2 a = g_a2s[sa];
        float2 b = g_a2s[sb];
        float hma = g_hmu[sa * 32 + lane];
        float hla = g_hlv[sa * 32 + lane];
        float hmb = g_hmu[sb * 32 + lane];
        float hlb = g_hlv[sb * 32 + lane];
        float la = a.x + ad.x; la = la > 0.f ? la : 0.2f * la; float wma = __expf(la - mmu);
        float lb = a.y + ad.y; lb = lb > 0.f ? lb : 0.2f * lb; float wla = __expf(lb - mlv);
        float lc = b.x + ad.x; lc = lc > 0.f ? lc : 0.2f * lc; float wmb = __expf(lc - mmu);
        float ld = b.y + ad.y; ld = ld > 0.f ? ld : 0.2f * ld; float wlb = __expf(ld - mlv);
        sm += wma + wmb; sl += wla + wlb;
        accm = fmaf(wma, hma, fmaf(wmb, hmb, accm));
        accl = fmaf(wla, hla, fmaf(wlb, hlb, accl));
    }
    if (i < end) {
        int sa = g_srcs[i];
        float2 a = g_a2s[sa];
        float hma = g_hmu[sa * 32 + lane];
        float hla = g_hlv[sa * 32 + lane];
        float la = a.x + ad.x; la = la > 0.f ? la : 0.2f * la; float wma = __expf(la - mmu);
        float lb = a.y + ad.y; lb = lb > 0.f ? lb : 0.2f * lb; float wla = __expf(lb - mlv);
        sm += wma; sl += wla;
        accm = fmaf(wma, hma, accm);
        accl = fmaf(wla, hla, accl);
    }
    out[n * 32 + lane]          = accm / (sm + 1e-16f) + bmu[lane];
    out[N * 32 + n * 32 + lane] = accl / (sl + 1e-16f) + blv[lane];
}

// ---------------- launch -----------------------------------------------------
extern "C" void kernel_launch(void* const* d_in, const int* in_sizes, int n_in,
                              void* d_out, int out_size) {
    const float* x          = (const float*)d_in[0];
    const int*   ei         = (const int*)d_in[1];
    const float* W1         = (const float*)d_in[2];
    const float* att_src1   = (const float*)d_in[3];
    const float* att_dst1   = (const float*)d_in[4];
    const float* b1         = (const float*)d_in[5];
    const float* Wmu        = (const float*)d_in[6];
    const float* att_src_mu = (const float*)d_in[7];
    const float* att_dst_mu = (const float*)d_in[8];
    const float* bmu        = (const float*)d_in[9];
    const float* Wlv        = (const float*)d_in[10];
    const float* att_src_lv = (const float*)d_in[11];
    const float* att_dst_lv = (const float*)d_in[12];
    const float* blv        = (const float*)d_in[13];
    float* out = (float*)d_out;

    int N = in_sizes[0] / 128;
    int E = in_sizes[1] / 2;
    int ET = E + N;

    float *h1p, *h2p, *hmup, *hlvp;
    cudaGetSymbolAddress((void**)&h1p, g_h1);
    cudaGetSymbolAddress((void**)&h2p, g_h2);
    cudaGetSymbolAddress((void**)&hmup, g_hmu);
    cudaGetSymbolAddress((void**)&hlvp, g_hlv);

    const int TB = 256;
    int warpBlocks = (N * 32 + TB - 1) / TB;

    // CSR build (by destination)
    zero_counts_kernel<<<(N + TB - 1) / TB, TB>>>(N);
    hist_kernel<<<(ET + TB - 1) / TB, TB>>>(ei, E, N);
    scan_kernel<<<1, 1024>>>(N, ET);
    scatter_kernel<<<(ET + TB - 1) / TB, TB>>>(ei, E, N);

    // Layer 1
    gemm_k128<128><<<(N + 63) / 64, TB>>>(x, W1, h1p, N);
    attdot1_kernel<<<warpBlocks, TB>>>(att_src1, att_dst1, N);
    agg1_kernel<<<warpBlocks, TB>>>(b1, N);

    // mu / logvar projections (fused layers share CSR and aggregation)
    gemm_k128<32><<<(N + 63) / 64, TB>>>(h2p, Wmu, hmup, N);
    gemm_k128<32><<<(N + 63) / 64, TB>>>(h2p, Wlv, hlvp, N);
    attdot2_kernel<<<warpBlocks, TB>>>(att_src_mu, att_dst_mu, att_src_lv, att_dst_lv, N);
    agg2_kernel<<<warpBlocks, TB>>>(bmu, blv, out, N);
}

// round 8
// speedup vs baseline: 1.5553x; 1.5553x over previous
#include <cuda_runtime.h>

// ---------------- problem-size capacities (fixed by the dataset) -------------
#define MAXN 50000
#define MAXE 800000
#define MAXET (MAXN + MAXE)
#define SCAN_CHUNK 4096
#define MAXNB ((MAXN + SCAN_CHUNK - 1) / SCAN_CHUNK)

// ---------------- device scratch (no allocation allowed) ---------------------
__device__ float g_h1[MAXN * 128];     // x @ W1
__device__ float g_h2[MAXN * 128];     // elu(layer1 out)
__device__ float g_hml[MAXN * 64];     // interleaved [mu_c, lv_c] pairs, c=0..31
__device__ float g_asrc1[MAXN * 2];    // layer1 per-node att dots (2 heads)
__device__ float g_adst1[MAXN * 2];
__device__ float2 g_a2s[MAXN];         // {a_src_mu, a_src_lv}
__device__ float2 g_a2d[MAXN];         // {a_dst_mu, a_dst_lv}
__device__ int   g_counts[MAXN];
__device__ int   g_row[MAXN + 1];
__device__ int   g_cursor[MAXN];
__device__ int   g_srcs[MAXET];        // CSR (by dst) of source node ids
__device__ int   g_part[MAXNB + 1];
__device__ int   g_partoff[MAXNB + 1];

// ---------------- CSR build --------------------------------------------------
__global__ void zero_counts_kernel(int n) {
    int i = blockIdx.x * blockDim.x + threadIdx.x;
    if (i < n) g_counts[i] = 0;
}

__global__ void hist_kernel(const int* __restrict__ ei, int E, int N) {
    int e = blockIdx.x * blockDim.x + threadIdx.x;
    int ET = E + N;
    if (e >= ET) return;
    int dst = (e < E) ? ei[E + e] : (e - E);   // self-loop tail
    atomicAdd(&g_counts[dst], 1);
}

__global__ void block_sum_kernel(int n) {
    int t = threadIdx.x;
    int base = blockIdx.x * SCAN_CHUNK + t * 4;
    int s = 0;
#pragma unroll
    for (int j = 0; j < 4; j++) { int i = base + j; if (i < n) s += g_counts[i]; }
#pragma unroll
    for (int off = 16; off; off >>= 1) s += __shfl_xor_sync(0xffffffffu, s, off);
    __shared__ int ws[32];
    if ((t & 31) == 0) ws[t >> 5] = s;
    __syncthreads();
    if (t < 32) {
        int v = ws[t];
#pragma unroll
        for (int off = 16; off; off >>= 1) v += __shfl_xor_sync(0xffffffffu, v, off);
        if (t == 0) g_part[blockIdx.x] = v;
    }
}

__global__ void part_scan_kernel(int nb, int Nn, int total) {
    int t = threadIdx.x;
    int v = (t < nb) ? g_part[t] : 0;
    int incl = v;
#pragma unroll
    for (int off = 1; off < 32; off <<= 1) {
        int y = __shfl_up_sync(0xffffffffu, incl, off);
        if (t >= off) incl += y;
    }
    if (t < nb) g_partoff[t] = incl - v;
    if (t == 0) g_row[Nn] = total;
}

__global__ void final_scan_kernel(int n) {
    int t = threadIdx.x, lane = t & 31, warp = t >> 5;
    int base = blockIdx.x * SCAN_CHUNK + t * 4;
    int v[4]; int s = 0;
#pragma unroll
    for (int j = 0; j < 4; j++) { int i = base + j; v[j] = (i < n) ? g_counts[i] : 0; s += v[j]; }
    int incl = s;
#pragma unroll
    for (int off = 1; off < 32; off <<= 1) {
        int y = __shfl_up_sync(0xffffffffu, incl, off);
        if (lane >= off) incl += y;
    }
    __shared__ int ws[32];
    if (lane == 31) ws[warp] = incl;
    __syncthreads();
    if (warp == 0) {
        int wv = ws[lane];
        int winc = wv;
#pragma unroll
        for (int off = 1; off < 32; off <<= 1) {
            int y = __shfl_up_sync(0xffffffffu, winc, off);
            if (lane >= off) winc += y;
        }
        ws[lane] = winc - wv;
    }
    __syncthreads();
    int running = g_partoff[blockIdx.x] + ws[warp] + (incl - s);
#pragma unroll
    for (int j = 0; j < 4; j++) {
        int i = base + j;
        if (i < n) { g_row[i] = running; g_cursor[i] = running; }
        running += v[j];
    }
}

__global__ void scatter_kernel(const int* __restrict__ ei, int E, int N) {
    int e = blockIdx.x * blockDim.x + threadIdx.x;
    int ET = E + N;
    if (e >= ET) return;
    int src, dst;
    if (e < E) { src = ei[e]; dst = ei[E + e]; }
    else       { src = e - E; dst = e - E; }
    int pos = atomicAdd(&g_cursor[dst], 1);
    g_srcs[pos] = src;
}

// ------- GEMM1: g_h1 = x @ W1  (+ fused layer-1 attention dot epilogue) ------
__global__ void gemm1_kernel(const float* __restrict__ A, const float* __restrict__ B,
                             const float* __restrict__ att_src, const float* __restrict__ att_dst,
                             int M) {
    constexpr int BM = 64, BK = 32, BN = 128;
    constexpr int TX = 32, TY = 8, RPT = 8;
    __shared__ float As[BK][BM + 1];
    __shared__ float Bs[BK][BN];
    int t = threadIdx.x;
    int tx = t % TX, ty = t / TX;
    int row0 = blockIdx.x * BM;
    float acc[RPT][4];
#pragma unroll
    for (int r = 0; r < RPT; r++) { acc[r][0] = acc[r][1] = acc[r][2] = acc[r][3] = 0.f; }

    for (int k0 = 0; k0 < 128; k0 += BK) {
        for (int i = t; i < BM * BK; i += 256) {
            int r = i / BK, kk = i % BK;
            int gr = row0 + r;
            As[kk][r] = (gr < M) ? A[gr * 128 + k0 + kk] : 0.f;
        }
        for (int i = t; i < BK * BN; i += 256) {
            int kk = i / BN, c = i % BN;
            Bs[kk][c] = B[(k0 + kk) * BN + c];
        }
        __syncthreads();
#pragma unroll
        for (int kk = 0; kk < BK; kk++) {
            float4 bv = *(const float4*)&Bs[kk][tx * 4];
#pragma unroll
            for (int r = 0; r < RPT; r++) {
                float a = As[kk][ty * RPT + r];
                acc[r][0] = fmaf(a, bv.x, acc[r][0]);
                acc[r][1] = fmaf(a, bv.y, acc[r][1]);
                acc[r][2] = fmaf(a, bv.z, acc[r][2]);
                acc[r][3] = fmaf(a, bv.w, acc[r][3]);
            }
        }
        __syncthreads();
    }
    float4 asv = *(const float4*)&att_src[tx * 4];
    float4 adv = *(const float4*)&att_dst[tx * 4];
#pragma unroll
    for (int r = 0; r < RPT; r++) {
        int gr = row0 + ty * RPT + r;
        bool ok = gr < M;
        if (ok)
            *(float4*)&g_h1[gr * 128 + tx * 4] =
                make_float4(acc[r][0], acc[r][1], acc[r][2], acc[r][3]);
        float ps = acc[r][0] * asv.x + acc[r][1] * asv.y + acc[r][2] * asv.z + acc[r][3] * asv.w;
        float pd = acc[r][0] * adv.x + acc[r][1] * adv.y + acc[r][2] * adv.z + acc[r][3] * adv.w;
#pragma unroll
        for (int off = 1; off < 16; off <<= 1) {   // reduce within 16-lane halves (per head)
            ps += __shfl_xor_sync(0xffffffffu, ps, off);
            pd += __shfl_xor_sync(0xffffffffu, pd, off);
        }
        if ((tx & 15) == 0 && ok) {
            g_asrc1[gr * 2 + (tx >> 4)] = ps;
            g_adst1[gr * 2 + (tx >> 4)] = pd;
        }
    }
}

// ---------------- layer-1 softmax + aggregation + bias + ELU -----------------
__global__ void agg1_kernel(const float* __restrict__ b1, int N) {
    int gid = blockIdx.x * blockDim.x + threadIdx.x;
    int n = gid >> 5, lane = gid & 31;
    if (n >= N) return;
    int start = g_row[n], end = g_row[n + 1];
    float2 ad = ((const float2*)g_adst1)[n];
    const float2* asrc2 = (const float2*)g_asrc1;
    int cb = lane * 4;
    bool head1 = lane >= 16;
    float a0 = 0.f, a1 = 0.f, a2 = 0.f, a3 = 0.f, s0 = 0.f, s1 = 0.f;

    for (int cs = start; cs < end; cs += 32) {
        int idx = cs + lane;
        int sp = g_srcs[idx < end ? idx : end - 1];
        float2 ap = asrc2[sp];
        float l0 = ap.x + ad.x; l0 = l0 > 0.f ? l0 : 0.2f * l0;
        float l1 = ap.y + ad.y; l1 = l1 > 0.f ? l1 : 0.2f * l1;
        float w0 = __expf(l0), w1 = __expf(l1);
        int cnt = min(32, end - cs);
        if (lane < cnt) { s0 += w0; s1 += w1; }
#pragma unroll 4
        for (int e = 0; e < cnt; e++) {
            // broadcast BOTH head weights of edge e; select by receiving lane's head
            float w0e = __shfl_sync(0xffffffffu, w0, e);
            float w1e = __shfl_sync(0xffffffffu, w1, e);
            int   s   = __shfl_sync(0xffffffffu, sp, e);
            float w = head1 ? w1e : w0e;
            float4 hv = *(const float4*)&g_h1[s * 128 + cb];
            a0 = fmaf(w, hv.x, a0);
            a1 = fmaf(w, hv.y, a1);
            a2 = fmaf(w, hv.z, a2);
            a3 = fmaf(w, hv.w, a3);
        }
    }
#pragma unroll
    for (int off = 16; off; off >>= 1) {
        s0 += __shfl_xor_sync(0xffffffffu, s0, off);
        s1 += __shfl_xor_sync(0xffffffffu, s1, off);
    }
    float inv = 1.f / ((head1 ? s1 : s0) + 1e-16f);
    float4 bb = *(const float4*)&b1[cb];
    float o0 = a0 * inv + bb.x; o0 = o0 > 0.f ? o0 : __expf(o0) - 1.f;
    float o1 = a1 * inv + bb.y; o1 = o1 > 0.f ? o1 : __expf(o1) - 1.f;
    float o2 = a2 * inv + bb.z; o2 = o2 > 0.f ? o2 : __expf(o2) - 1.f;
    float o3 = a3 * inv + bb.w; o3 = o3 > 0.f ? o3 : __expf(o3) - 1.f;
    *(float4*)&g_h2[n * 128 + cb] = make_float4(o0, o1, o2, o3);
}

// ------- fused mu+lv GEMM: g_hml = h2 @ [Wmu | Wlv] (interleaved) + dots -----
__global__ void gemm_mulv_kernel(const float* __restrict__ Bmu, const float* __restrict__ Blv,
                                 const float* __restrict__ asmu, const float* __restrict__ admu,
                                 const float* __restrict__ aslv, const float* __restrict__ adlv,
                                 int M) {
    constexpr int BM = 64, BK = 32, BN = 64;
    constexpr int TX = 16, TY = 16, RPT = 4;
    __shared__ float As[BK][BM + 1];
    __shared__ float Bs[BK][BN];
    int t = threadIdx.x;
    int tx = t % TX, ty = t / TX;
    int row0 = blockIdx.x * BM;
    float acc[RPT][4];
#pragma unroll
    for (int r = 0; r < RPT; r++) { acc[r][0] = acc[r][1] = acc[r][2] = acc[r][3] = 0.f; }

    for (int k0 = 0; k0 < 128; k0 += BK) {
        for (int i = t; i < BM * BK; i += 256) {
            int r = i / BK, kk = i % BK;
            int gr = row0 + r;
            As[kk][r] = (gr < M) ? g_h2[gr * 128 + k0 + kk] : 0.f;
        }
        for (int i = t; i < BK * BN; i += 256) {
            int kk = i / BN, c = i % BN;
            Bs[kk][c] = (c < 32) ? Bmu[(k0 + kk) * 32 + c] : Blv[(k0 + kk) * 32 + (c - 32)];
        }
        __syncthreads();
#pragma unroll
        for (int kk = 0; kk < BK; kk++) {
            float4 bv = *(const float4*)&Bs[kk][tx * 4];
#pragma unroll
            for (int r = 0; r < RPT; r++) {
                float a = As[kk][ty * RPT + r];
                acc[r][0] = fmaf(a, bv.x, acc[r][0]);
                acc[r][1] = fmaf(a, bv.y, acc[r][1]);
                acc[r][2] = fmaf(a, bv.z, acc[r][2]);
                acc[r][3] = fmaf(a, bv.w, acc[r][3]);
            }
        }
        __syncthreads();
    }
    bool islv = tx >= 8;
    int c0 = (tx * 4) & 31;   // channel base within the 32-dim latent
    float4 asv = islv ? *(const float4*)&aslv[c0] : *(const float4*)&asmu[c0];
    float4 adv = islv ? *(const float4*)&adlv[c0] : *(const float4*)&admu[c0];
#pragma unroll
    for (int r = 0; r < RPT; r++) {
        int gr = row0 + ty * RPT + r;
        bool ok = gr < M;
        if (ok) {
            // interleaved: mu channel c -> [gr*64 + 2c], lv channel c -> [gr*64 + 2c+1]
            g_hml[gr * 64 + 2 * (c0 + 0) + islv] = acc[r][0];
            g_hml[gr * 64 + 2 * (c0 + 1) + islv] = acc[r][1];
            g_hml[gr * 64 + 2 * (c0 + 2) + islv] = acc[r][2];
            g_hml[gr * 64 + 2 * (c0 + 3) + islv] = acc[r][3];
        }
        float ps = acc[r][0] * asv.x + acc[r][1] * asv.y + acc[r][2] * asv.z + acc[r][3] * asv.w;
        float pd = acc[r][0] * adv.x + acc[r][1] * adv.y + acc[r][2] * adv.z + acc[r][3] * adv.w;
#pragma unroll
        for (int off = 1; off < 8; off <<= 1) {    // reduce within 8-lane subgroup
            ps += __shfl_xor_sync(0xffffffffu, ps, off);
            pd += __shfl_xor_sync(0xffffffffu, pd, off);
        }
        float os = __shfl_xor_sync(0xffffffffu, ps, 8);  // grab the other net's sum
        float od = __shfl_xor_sync(0xffffffffu, pd, 8);
        if ((t & 15) == 0 && ok) {
            g_a2s[gr] = make_float2(ps, os);   // {mu, lv}
            g_a2d[gr] = make_float2(pd, od);
        }
    }
}

// ---------------- mu + lv softmax + aggregation (fused), writes output -------
__global__ void agg2_kernel(const float* __restrict__ bmu, const float* __restrict__ blv,
                            float* __restrict__ out, int N) {
    int gid = blockIdx.x * blockDim.x + threadIdx.x;
    int n = gid >> 5, lane = gid & 31;
    if (n >= N) return;
    int start = g_row[n], end = g_row[n + 1];
    float2 ad = g_a2d[n];
    const float2* hml2 = (const float2*)g_hml;
    float accm = 0.f, accl = 0.f, sm = 0.f, sl = 0.f;

    for (int cs = start; cs < end; cs += 32) {
        int idx = cs + lane;
        int sp = g_srcs[idx < end ? idx : end - 1];
        float2 ap = g_a2s[sp];
        float lm = ap.x + ad.x; lm = lm > 0.f ? lm : 0.2f * lm;
        float ll = ap.y + ad.y; ll = ll > 0.f ? ll : 0.2f * ll;
        float wm = __expf(lm), wl = __expf(ll);
        int cnt = min(32, end - cs);
        if (lane < cnt) { sm += wm; sl += wl; }
#pragma unroll 4
        for (int e = 0; e < cnt; e++) {
            float wme = __shfl_sync(0xffffffffu, wm, e);
            float wle = __shfl_sync(0xffffffffu, wl, e);
            int   s   = __shfl_sync(0xffffffffu, sp, e);
            float2 hv = hml2[s * 32 + lane];   // {mu_c, lv_c}, c = lane
            accm = fmaf(wme, hv.x, accm);
            accl = fmaf(wle, hv.y, accl);
        }
    }
#pragma unroll
    for (int off = 16; off; off >>= 1) {
        sm += __shfl_xor_sync(0xffffffffu, sm, off);
        sl += __shfl_xor_sync(0xffffffffu, sl, off);
    }
    out[n * 32 + lane]          = accm / (sm + 1e-16f) + bmu[lane];
    out[N * 32 + n * 32 + lane] = accl / (sl + 1e-16f) + blv[lane];
}

// ---------------- launch -----------------------------------------------------
extern "C" void kernel_launch(void* const* d_in, const int* in_sizes, int n_in,
                              void* d_out, int out_size) {
    const float* x          = (const float*)d_in[0];
    const int*   ei         = (const int*)d_in[1];
    const float* W1         = (const float*)d_in[2];
    const float* att_src1   = (const float*)d_in[3];
    const float* att_dst1   = (const float*)d_in[4];
    const float* b1         = (const float*)d_in[5];
    const float* Wmu        = (const float*)d_in[6];
    const float* att_src_mu = (const float*)d_in[7];
    const float* att_dst_mu = (const float*)d_in[8];
    const float* bmu        = (const float*)d_in[9];
    const float* Wlv        = (const float*)d_in[10];
    const float* att_src_lv = (const float*)d_in[11];
    const float* att_dst_lv = (const float*)d_in[12];
    const float* blv        = (const float*)d_in[13];
    float* out = (float*)d_out;

    int N = in_sizes[0] / 128;
    int E = in_sizes[1] / 2;
    int ET = E + N;
    int NB = (N + SCAN_CHUNK - 1) / SCAN_CHUNK;

    const int TB = 256;
    int warpBlocks = (N * 32 + TB - 1) / TB;

    // CSR build (by destination)
    zero_counts_kernel<<<(N + TB - 1) / TB, TB>>>(N);
    hist_kernel<<<(ET + TB - 1) / TB, TB>>>(ei, E, N);
    block_sum_kernel<<<NB, 1024>>>(N);
    part_scan_kernel<<<1, 32>>>(NB, N, ET);
    final_scan_kernel<<<NB, 1024>>>(N);
    scatter_kernel<<<(ET + TB - 1) / TB, TB>>>(ei, E, N);

    // Layer 1 (attention dots fused into GEMM epilogue)
    gemm1_kernel<<<(N + 63) / 64, TB>>>(x, W1, att_src1, att_dst1, N);
    agg1_kernel<<<warpBlocks, TB>>>(b1, N);

    // mu + logvar: fused projection GEMM (+dots), fused aggregation
    gemm_mulv_kernel<<<(N + 63) / 64, TB>>>(Wmu, Wlv, att_src_mu, att_dst_mu,
                                            att_src_lv, att_dst_lv, N);
    agg2_kernel<<<warpBlocks, TB>>>(bmu, blv, out, N);
}

// round 9
// speedup vs baseline: 1.6074x; 1.0335x over previous
#include <cuda_runtime.h>
#include <cuda_fp16.h>

// ---------------- problem-size capacities (fixed by the dataset) -------------
#define MAXN 50000
#define MAXE 800000
#define MAXET (MAXN + MAXE)
#define SCAN_CHUNK 4096
#define MAXNB ((MAXN + SCAN_CHUNK - 1) / SCAN_CHUNK)

// ---------------- device scratch (no allocation allowed) ---------------------
__device__ __half g_h1h[MAXN * 128];   // x @ W1   (fp16, gather-only)
__device__ float  g_h2[MAXN * 128];    // elu(layer1 out)  (fp32, GEMM input)
__device__ __half g_hmlh[MAXN * 64];   // interleaved [mu_c, lv_c], fp16, gather-only
__device__ float  g_asrc1[MAXN * 2];   // layer1 per-node att dots (2 heads)
__device__ float  g_adst1[MAXN * 2];
__device__ float2 g_a2s[MAXN];         // {a_src_mu, a_src_lv}
__device__ float2 g_a2d[MAXN];         // {a_dst_mu, a_dst_lv}
__device__ int    g_counts[MAXN];
__device__ int    g_row[MAXN + 1];
__device__ int    g_cursor[MAXN];
__device__ int    g_srcs[MAXET];       // CSR (by dst) of source node ids
__device__ int    g_part[MAXNB + 1];

// ---------------- CSR build --------------------------------------------------
__global__ void zero_counts_kernel(int n) {
    int i = blockIdx.x * blockDim.x + threadIdx.x;
    if (i < n) g_counts[i] = 0;
}

__global__ void hist_kernel(const int* __restrict__ ei, int E, int N) {
    int e = blockIdx.x * blockDim.x + threadIdx.x;
    int ET = E + N;
    if (e >= ET) return;
    int dst = (e < E) ? ei[E + e] : (e - E);   // self-loop tail
    atomicAdd(&g_counts[dst], 1);
}

__global__ void block_sum_kernel(int n) {
    int t = threadIdx.x;
    int base = blockIdx.x * SCAN_CHUNK + t * 4;
    int s = 0;
#pragma unroll
    for (int j = 0; j < 4; j++) { int i = base + j; if (i < n) s += g_counts[i]; }
#pragma unroll
    for (int off = 16; off; off >>= 1) s += __shfl_xor_sync(0xffffffffu, s, off);
    __shared__ int ws[32];
    if ((t & 31) == 0) ws[t >> 5] = s;
    __syncthreads();
    if (t < 32) {
        int v = ws[t];
#pragma unroll
        for (int off = 16; off; off >>= 1) v += __shfl_xor_sync(0xffffffffu, v, off);
        if (t == 0) g_part[blockIdx.x] = v;
    }
}

// final scan: per-block scan + in-kernel partial-block offset (g_part is tiny)
__global__ void final_scan_kernel(int n, int nb, int total) {
    int t = threadIdx.x, lane = t & 31, warp = t >> 5;
    __shared__ int s_partoff;
    __shared__ int ws[32];
    if (t < 32) {
        int v = (lane < nb && lane < blockIdx.x) ? g_part[lane] : 0;
#pragma unroll
        for (int off = 16; off; off >>= 1) v += __shfl_xor_sync(0xffffffffu, v, off);
        if (lane == 0) s_partoff = v;
    }
    int base = blockIdx.x * SCAN_CHUNK + t * 4;
    int v[4]; int s = 0;
#pragma unroll
    for (int j = 0; j < 4; j++) { int i = base + j; v[j] = (i < n) ? g_counts[i] : 0; s += v[j]; }
    int incl = s;
#pragma unroll
    for (int off = 1; off < 32; off <<= 1) {
        int y = __shfl_up_sync(0xffffffffu, incl, off);
        if (lane >= off) incl += y;
    }
    if (lane == 31) ws[warp] = incl;
    __syncthreads();
    if (warp == 0) {
        int wv = ws[lane];
        int winc = wv;
#pragma unroll
        for (int off = 1; off < 32; off <<= 1) {
            int y = __shfl_up_sync(0xffffffffu, winc, off);
            if (lane >= off) winc += y;
        }
        ws[lane] = winc - wv;
    }
    __syncthreads();
    int running = s_partoff + ws[warp] + (incl - s);
#pragma unroll
    for (int j = 0; j < 4; j++) {
        int i = base + j;
        if (i < n) { g_row[i] = running; g_cursor[i] = running; }
        running += v[j];
    }
    if (blockIdx.x == 0 && t == 0) g_row[n] = total;
}

__global__ void scatter_kernel(const int* __restrict__ ei, int E, int N) {
    int e = blockIdx.x * blockDim.x + threadIdx.x;
    int ET = E + N;
    if (e >= ET) return;
    int src, dst;
    if (e < E) { src = ei[e]; dst = ei[E + e]; }
    else       { src = e - E; dst = e - E; }
    int pos = atomicAdd(&g_cursor[dst], 1);
    g_srcs[pos] = src;
}

// ------- GEMM1: g_h1h = half(x @ W1)  (+ fused layer-1 attention dots) -------
__global__ void gemm1_kernel(const float* __restrict__ A, const float* __restrict__ B,
                             const float* __restrict__ att_src, const float* __restrict__ att_dst,
                             int M) {
    constexpr int BM = 64, BK = 32, BN = 128;
    constexpr int TX = 32, TY = 8, RPT = 8;
    __shared__ float As[BK][BM + 1];
    __shared__ float Bs[BK][BN];
    int t = threadIdx.x;
    int tx = t % TX, ty = t / TX;
    int row0 = blockIdx.x * BM;
    float acc[RPT][4];
#pragma unroll
    for (int r = 0; r < RPT; r++) { acc[r][0] = acc[r][1] = acc[r][2] = acc[r][3] = 0.f; }

    for (int k0 = 0; k0 < 128; k0 += BK) {
        for (int i = t; i < BM * BK; i += 256) {
            int r = i / BK, kk = i % BK;
            int gr = row0 + r;
            As[kk][r] = (gr < M) ? A[gr * 128 + k0 + kk] : 0.f;
        }
        for (int i = t; i < BK * BN; i += 256) {
            int kk = i / BN, c = i % BN;
            Bs[kk][c] = B[(k0 + kk) * BN + c];
        }
        __syncthreads();
#pragma unroll
        for (int kk = 0; kk < BK; kk++) {
            float4 bv = *(const float4*)&Bs[kk][tx * 4];
#pragma unroll
            for (int r = 0; r < RPT; r++) {
                float a = As[kk][ty * RPT + r];
                acc[r][0] = fmaf(a, bv.x, acc[r][0]);
                acc[r][1] = fmaf(a, bv.y, acc[r][1]);
                acc[r][2] = fmaf(a, bv.z, acc[r][2]);
                acc[r][3] = fmaf(a, bv.w, acc[r][3]);
            }
        }
        __syncthreads();
    }
    float4 asv = *(const float4*)&att_src[tx * 4];
    float4 adv = *(const float4*)&att_dst[tx * 4];
#pragma unroll
    for (int r = 0; r < RPT; r++) {
        int gr = row0 + ty * RPT + r;
        bool ok = gr < M;
        if (ok) {
            __half2 p0 = __floats2half2_rn(acc[r][0], acc[r][1]);
            __half2 p1 = __floats2half2_rn(acc[r][2], acc[r][3]);
            uint2 pk;
            pk.x = *(unsigned int*)&p0;
            pk.y = *(unsigned int*)&p1;
            *(uint2*)&g_h1h[gr * 128 + tx * 4] = pk;
        }
        float ps = acc[r][0] * asv.x + acc[r][1] * asv.y + acc[r][2] * asv.z + acc[r][3] * asv.w;
        float pd = acc[r][0] * adv.x + acc[r][1] * adv.y + acc[r][2] * adv.z + acc[r][3] * adv.w;
#pragma unroll
        for (int off = 1; off < 16; off <<= 1) {   // reduce within 16-lane halves (per head)
            ps += __shfl_xor_sync(0xffffffffu, ps, off);
            pd += __shfl_xor_sync(0xffffffffu, pd, off);
        }
        if ((tx & 15) == 0 && ok) {
            g_asrc1[gr * 2 + (tx >> 4)] = ps;
            g_adst1[gr * 2 + (tx >> 4)] = pd;
        }
    }
}

// ---------------- layer-1 softmax + aggregation + bias + ELU -----------------
__global__ void agg1_kernel(const float* __restrict__ b1, int N) {
    int gid = blockIdx.x * blockDim.x + threadIdx.x;
    int n = gid >> 5, lane = gid & 31;
    if (n >= N) return;
    int start = g_row[n], end = g_row[n + 1];
    float2 ad = ((const float2*)g_adst1)[n];
    const float2* asrc2 = (const float2*)g_asrc1;
    int cb = lane * 4;
    bool head1 = lane >= 16;
    float a0 = 0.f, a1 = 0.f, a2 = 0.f, a3 = 0.f, s0 = 0.f, s1 = 0.f;

    for (int cs = start; cs < end; cs += 32) {
        int idx = cs + lane;
        int sp = g_srcs[idx < end ? idx : end - 1];
        float2 ap = asrc2[sp];
        float l0 = ap.x + ad.x; l0 = l0 > 0.f ? l0 : 0.2f * l0;
        float l1 = ap.y + ad.y; l1 = l1 > 0.f ? l1 : 0.2f * l1;
        float w0 = __expf(l0), w1 = __expf(l1);
        int cnt = min(32, end - cs);
        if (lane < cnt) { s0 += w0; s1 += w1; }
#pragma unroll 4
        for (int e = 0; e < cnt; e++) {
            float w0e = __shfl_sync(0xffffffffu, w0, e);
            float w1e = __shfl_sync(0xffffffffu, w1, e);
            int   s   = __shfl_sync(0xffffffffu, sp, e);
            float w = head1 ? w1e : w0e;
            uint2 raw = *(const uint2*)&g_h1h[s * 128 + cb];
            float2 f0 = __half22float2(*(__half2*)&raw.x);
            float2 f1 = __half22float2(*(__half2*)&raw.y);
            a0 = fmaf(w, f0.x, a0);
            a1 = fmaf(w, f0.y, a1);
            a2 = fmaf(w, f1.x, a2);
            a3 = fmaf(w, f1.y, a3);
        }
    }
#pragma unroll
    for (int off = 16; off; off >>= 1) {
        s0 += __shfl_xor_sync(0xffffffffu, s0, off);
        s1 += __shfl_xor_sync(0xffffffffu, s1, off);
    }
    float inv = 1.f / ((head1 ? s1 : s0) + 1e-16f);
    float4 bb = *(const float4*)&b1[cb];
    float o0 = a0 * inv + bb.x; o0 = o0 > 0.f ? o0 : __expf(o0) - 1.f;
    float o1 = a1 * inv + bb.y; o1 = o1 > 0.f ? o1 : __expf(o1) - 1.f;
    float o2 = a2 * inv + bb.z; o2 = o2 > 0.f ? o2 : __expf(o2) - 1.f;
    float o3 = a3 * inv + bb.w; o3 = o3 > 0.f ? o3 : __expf(o3) - 1.f;
    *(float4*)&g_h2[n * 128 + cb] = make_float4(o0, o1, o2, o3);
}

// ------- fused mu+lv GEMM: g_hmlh = half(h2 @ [Wmu | Wlv]) + dots ------------
__global__ void gemm_mulv_kernel(const float* __restrict__ Bmu, const float* __restrict__ Blv,
                                 const float* __restrict__ asmu, const float* __restrict__ admu,
                                 const float* __restrict__ aslv, const float* __restrict__ adlv,
                                 int M) {
    constexpr int BM = 64, BK = 32, BN = 64;
    constexpr int TX = 16, TY = 16, RPT = 4;
    __shared__ float As[BK][BM + 1];
    __shared__ float Bs[BK][BN];
    int t = threadIdx.x;
    int tx = t % TX, ty = t / TX;
    int row0 = blockIdx.x * BM;
    float acc[RPT][4];
#pragma unroll
    for (int r = 0; r < RPT; r++) { acc[r][0] = acc[r][1] = acc[r][2] = acc[r][3] = 0.f; }

    for (int k0 = 0; k0 < 128; k0 += BK) {
        for (int i = t; i < BM * BK; i += 256) {
            int r = i / BK, kk = i % BK;
            int gr = row0 + r;
            As[kk][r] = (gr < M) ? g_h2[gr * 128 + k0 + kk] : 0.f;
        }
        for (int i = t; i < BK * BN; i += 256) {
            int kk = i / BN, c = i % BN;
            Bs[kk][c] = (c < 32) ? Bmu[(k0 + kk) * 32 + c] : Blv[(k0 + kk) * 32 + (c - 32)];
        }
        __syncthreads();
#pragma unroll
        for (int kk = 0; kk < BK; kk++) {
            float4 bv = *(const float4*)&Bs[kk][tx * 4];
#pragma unroll
            for (int r = 0; r < RPT; r++) {
                float a = As[kk][ty * RPT + r];
                acc[r][0] = fmaf(a, bv.x, acc[r][0]);
                acc[r][1] = fmaf(a, bv.y, acc[r][1]);
                acc[r][2] = fmaf(a, bv.z, acc[r][2]);
                acc[r][3] = fmaf(a, bv.w, acc[r][3]);
            }
        }
        __syncthreads();
    }
    bool islv = tx >= 8;
    int c0 = (tx * 4) & 31;   // channel base within the 32-dim latent
    float4 asv = islv ? *(const float4*)&aslv[c0] : *(const float4*)&asmu[c0];
    float4 adv = islv ? *(const float4*)&adlv[c0] : *(const float4*)&admu[c0];
#pragma unroll
    for (int r = 0; r < RPT; r++) {
        int gr = row0 + ty * RPT + r;
        bool ok = gr < M;
        if (ok) {
            // interleaved: mu channel c -> [gr*64 + 2c], lv channel c -> [gr*64 + 2c+1]
            g_hmlh[gr * 64 + 2 * (c0 + 0) + islv] = __float2half_rn(acc[r][0]);
            g_hmlh[gr * 64 + 2 * (c0 + 1) + islv] = __float2half_rn(acc[r][1]);
            g_hmlh[gr * 64 + 2 * (c0 + 2) + islv] = __float2half_rn(acc[r][2]);
            g_hmlh[gr * 64 + 2 * (c0 + 3) + islv] = __float2half_rn(acc[r][3]);
        }
        float ps = acc[r][0] * asv.x + acc[r][1] * asv.y + acc[r][2] * asv.z + acc[r][3] * asv.w;
        float pd = acc[r][0] * adv.x + acc[r][1] * adv.y + acc[r][2] * adv.z + acc[r][3] * adv.w;
#pragma unroll
        for (int off = 1; off < 8; off <<= 1) {    // reduce within 8-lane subgroup
            ps += __shfl_xor_sync(0xffffffffu, ps, off);
            pd += __shfl_xor_sync(0xffffffffu, pd, off);
        }
        float os = __shfl_xor_sync(0xffffffffu, ps, 8);  // grab the other net's sum
        float od = __shfl_xor_sync(0xffffffffu, pd, 8);
        if ((t & 15) == 0 && ok) {
            g_a2s[gr] = make_float2(ps, os);   // {mu, lv}
            g_a2d[gr] = make_float2(pd, od);
        }
    }
}

// ---------------- mu + lv softmax + aggregation (fused), writes output -------
__global__ void agg2_kernel(const float* __restrict__ bmu, const float* __restrict__ blv,
                            float* __restrict__ out, int N) {
    int gid = blockIdx.x * blockDim.x + threadIdx.x;
    int n = gid >> 5, lane = gid & 31;
    if (n >= N) return;
    int start = g_row[n], end = g_row[n + 1];
    float2 ad = g_a2d[n];
    float accm = 0.f, accl = 0.f, sm = 0.f, sl = 0.f;

    for (int cs = start; cs < end; cs += 32) {
        int idx = cs + lane;
        int sp = g_srcs[idx < end ? idx : end - 1];
        float2 ap = g_a2s[sp];
        float lm = ap.x + ad.x; lm = lm > 0.f ? lm : 0.2f * lm;
        float ll = ap.y + ad.y; ll = ll > 0.f ? ll : 0.2f * ll;
        float wm = __expf(lm), wl = __expf(ll);
        int cnt = min(32, end - cs);
        if (lane < cnt) { sm += wm; sl += wl; }
#pragma unroll 4
        for (int e = 0; e < cnt; e++) {
            float wme = __shfl_sync(0xffffffffu, wm, e);
            float wle = __shfl_sync(0xffffffffu, wl, e);
            int   s   = __shfl_sync(0xffffffffu, sp, e);
            __half2 hv = *(const __half2*)&g_hmlh[s * 64 + lane * 2];  // {mu_c, lv_c}
            float2 f = __half22float2(hv);
            accm = fmaf(wme, f.x, accm);
            accl = fmaf(wle, f.y, accl);
        }
    }
#pragma unroll
    for (int off = 16; off; off >>= 1) {
        sm += __shfl_xor_sync(0xffffffffu, sm, off);
        sl += __shfl_xor_sync(0xffffffffu, sl, off);
    }
    out[n * 32 + lane]          = accm / (sm + 1e-16f) + bmu[lane];
    out[N * 32 + n * 32 + lane] = accl / (sl + 1e-16f) + blv[lane];
}

// ---------------- launch -----------------------------------------------------
extern "C" void kernel_launch(void* const* d_in, const int* in_sizes, int n_in,
                              void* d_out, int out_size) {
    const float* x          = (const float*)d_in[0];
    const int*   ei         = (const int*)d_in[1];
    const float* W1         = (const float*)d_in[2];
    const float* att_src1   = (const float*)d_in[3];
    const float* att_dst1   = (const float*)d_in[4];
    const float* b1         = (const float*)d_in[5];
    const float* Wmu        = (const float*)d_in[6];
    const float* att_src_mu = (const float*)d_in[7];
    const float* att_dst_mu = (const float*)d_in[8];
    const float* bmu        = (const float*)d_in[9];
    const float* Wlv        = (const float*)d_in[10];
    const float* att_src_lv = (const float*)d_in[11];
    const float* att_dst_lv = (const float*)d_in[12];
    const float* blv        = (const float*)d_in[13];
    float* out = (float*)d_out;

    int N = in_sizes[0] / 128;
    int E = in_sizes[1] / 2;
    int ET = E + N;
    int NB = (N + SCAN_CHUNK - 1) / SCAN_CHUNK;

    const int TB = 256;
    int warpBlocks = (N * 32 + TB - 1) / TB;

    // CSR build (by destination)
    zero_counts_kernel<<<(N + TB - 1) / TB, TB>>>(N);
    hist_kernel<<<(ET + TB - 1) / TB, TB>>>(ei, E, N);
    block_sum_kernel<<<NB, 1024>>>(N);
    final_scan_kernel<<<NB, 1024>>>(N, NB, ET);
    scatter_kernel<<<(ET + TB - 1) / TB, TB>>>(ei, E, N);

    // Layer 1 (attention dots fused into GEMM epilogue)
    gemm1_kernel<<<(N + 63) / 64, TB>>>(x, W1, att_src1, att_dst1, N);
    agg1_kernel<<<warpBlocks, TB>>>(b1, N);

    // mu + logvar: fused projection GEMM (+dots), fused aggregation
    gemm_mulv_kernel<<<(N + 63) / 64, TB>>>(Wmu, Wlv, att_src_mu, att_dst_mu,
                                            att_src_lv, att_dst_lv, N);
    agg2_kernel<<<warpBlocks, TB>>>(bmu, blv, out, N);
}

// round 12
// speedup vs baseline: 1.6812x; 1.0459x over previous
#include <cuda_runtime.h>
#include <cuda_fp16.h>

// ---------------- problem-size capacities (fixed by the dataset) -------------
#define MAXN 50000
#define MAXE 800000
#define MAXET (MAXN + MAXE)
#define SCAN_CHUNK 4096
#define MAXNB ((MAXN + SCAN_CHUNK - 1) / SCAN_CHUNK)

// ---------------- device scratch (no allocation allowed) ---------------------
__device__ __half g_h1h[MAXN * 128];   // x @ W1   (fp16, gather-only)
__device__ float  g_h2[MAXN * 128];    // elu(layer1 out)  (fp32, GEMM input)
__device__ __half g_hmlh[MAXN * 64];   // interleaved [mu_c, lv_c], fp16, gather-only
__device__ float  g_asrc1[MAXN * 2];   // layer1 per-node att dots (2 heads)
__device__ float  g_adst1[MAXN * 2];
__device__ float2 g_a2s[MAXN];         // {a_src_mu, a_src_lv}
__device__ float2 g_a2d[MAXN];         // {a_dst_mu, a_dst_lv}
__device__ int    g_counts[MAXN];
__device__ int    g_row[MAXN + 1];
__device__ int    g_cursor[MAXN];
__device__ int    g_srcs[MAXET];       // CSR (by dst) of source node ids
__device__ int    g_dsts[MAXET];       // CSR slot -> dst node id
__device__ int    g_part[MAXNB + 1];
__device__ float4 g_e1[MAXET];         // per-edge {w0, w1, src_bits, -} layer 1
__device__ float4 g_e2[MAXET];         // per-edge {wmu, wlv, src_bits, -} layer 2

// ---------------- CSR build --------------------------------------------------
__global__ void zero_counts_kernel(int n) {
    int i = blockIdx.x * blockDim.x + threadIdx.x;
    if (i < n) g_counts[i] = 0;
}

__global__ void hist_kernel(const int* __restrict__ ei, int E, int N) {
    int e = blockIdx.x * blockDim.x + threadIdx.x;
    int ET = E + N;
    if (e >= ET) return;
    int dst = (e < E) ? ei[E + e] : (e - E);   // self-loop tail
    atomicAdd(&g_counts[dst], 1);
}

__global__ void block_sum_kernel(int n) {
    int t = threadIdx.x;
    int base = blockIdx.x * SCAN_CHUNK + t * 4;
    int s = 0;
#pragma unroll
    for (int j = 0; j < 4; j++) { int i = base + j; if (i < n) s += g_counts[i]; }
#pragma unroll
    for (int off = 16; off; off >>= 1) s += __shfl_xor_sync(0xffffffffu, s, off);
    __shared__ int ws[32];
    if ((t & 31) == 0) ws[t >> 5] = s;
    __syncthreads();
    if (t < 32) {
        int v = ws[t];
#pragma unroll
        for (int off = 16; off; off >>= 1) v += __shfl_xor_sync(0xffffffffu, v, off);
        if (t == 0) g_part[blockIdx.x] = v;
    }
}

// final scan: per-block scan + in-kernel partial-block offset (g_part is tiny)
__global__ void final_scan_kernel(int n, int nb, int total) {
    int t = threadIdx.x, lane = t & 31, warp = t >> 5;
    __shared__ int s_partoff;
    __shared__ int ws[32];
    if (t < 32) {
        int v = (lane < nb && lane < blockIdx.x) ? g_part[lane] : 0;
#pragma unroll
        for (int off = 16; off; off >>= 1) v += __shfl_xor_sync(0xffffffffu, v, off);
        if (lane == 0) s_partoff = v;
    }
    int base = blockIdx.x * SCAN_CHUNK + t * 4;
    int v[4]; int s = 0;
#pragma unroll
    for (int j = 0; j < 4; j++) { int i = base + j; v[j] = (i < n) ? g_counts[i] : 0; s += v[j]; }
    int incl = s;
#pragma unroll
    for (int off = 1; off < 32; off <<= 1) {
        int y = __shfl_up_sync(0xffffffffu, incl, off);
        if (lane >= off) incl += y;
    }
    if (lane == 31) ws[warp] = incl;
    __syncthreads();
    if (warp == 0) {
        int wv = ws[lane];
        int winc = wv;
#pragma unroll
        for (int off = 1; off < 32; off <<= 1) {
            int y = __shfl_up_sync(0xffffffffu, winc, off);
            if (lane >= off) winc += y;
        }
        ws[lane] = winc - wv;
    }
    __syncthreads();
    int running = s_partoff + ws[warp] + (incl - s);
#pragma unroll
    for (int j = 0; j < 4; j++) {
        int i = base + j;
        if (i < n) { g_row[i] = running; g_cursor[i] = running; }
        running += v[j];
    }
    if (blockIdx.x == 0 && t == 0) g_row[n] = total;
}

__global__ void scatter_kernel(const int* __restrict__ ei, int E, int N) {
    int e = blockIdx.x * blockDim.x + threadIdx.x;
    int ET = E + N;
    if (e >= ET) return;
    int src, dst;
    if (e < E) { src = ei[e]; dst = ei[E + e]; }
    else       { src = e - E; dst = e - E; }
    int pos = atomicAdd(&g_cursor[dst], 1);
    g_srcs[pos] = src;
    g_dsts[pos] = dst;
}

// ------- per-edge weight precompute (device-global tables, coalesced I/O) ----
__global__ void weight1_kernel(int ET) {
    int e = blockIdx.x * blockDim.x + threadIdx.x;
    if (e >= ET) return;
    int s = g_srcs[e], d = g_dsts[e];
    float2 a = ((const float2*)g_asrc1)[s];
    float2 b = ((const float2*)g_adst1)[d];
    float l0 = a.x + b.x; l0 = l0 > 0.f ? l0 : 0.2f * l0;
    float l1 = a.y + b.y; l1 = l1 > 0.f ? l1 : 0.2f * l1;
    g_e1[e] = make_float4(__expf(l0), __expf(l1), __int_as_float(s), 0.f);
}

__global__ void weight2_kernel(int ET) {
    int e = blockIdx.x * blockDim.x + threadIdx.x;
    if (e >= ET) return;
    int s = g_srcs[e], d = g_dsts[e];
    float2 a = g_a2s[s];
    float2 b = g_a2d[d];
    float l0 = a.x + b.x; l0 = l0 > 0.f ? l0 : 0.2f * l0;
    float l1 = a.y + b.y; l1 = l1 > 0.f ? l1 : 0.2f * l1;
    g_e2[e] = make_float4(__expf(l0), __expf(l1), __int_as_float(s), 0.f);
}

// ------- GEMM1: g_h1h = half(x @ W1)  (+ fused layer-1 attention dots) -------
__global__ void gemm1_kernel(const float* __restrict__ A, const float* __restrict__ B,
                             const float* __restrict__ att_src, const float* __restrict__ att_dst,
                             int M) {
    constexpr int BM = 64, BK = 32, BN = 128;
    constexpr int TX = 32, TY = 8, RPT = 8;
    __shared__ float As[BK][BM + 1];
    __shared__ float Bs[BK][BN];
    int t = threadIdx.x;
    int tx = t % TX, ty = t / TX;
    int row0 = blockIdx.x * BM;
    float acc[RPT][4];
#pragma unroll
    for (int r = 0; r < RPT; r++) { acc[r][0] = acc[r][1] = acc[r][2] = acc[r][3] = 0.f; }

    for (int k0 = 0; k0 < 128; k0 += BK) {
        for (int i = t; i < BM * BK; i += 256) {
            int r = i / BK, kk = i % BK;
            int gr = row0 + r;
            As[kk][r] = (gr < M) ? A[gr * 128 + k0 + kk] : 0.f;
        }
        for (int i = t; i < BK * BN; i += 256) {
            int kk = i / BN, c = i % BN;
            Bs[kk][c] = B[(k0 + kk) * BN + c];
        }
        __syncthreads();
#pragma unroll
        for (int kk = 0; kk < BK; kk++) {
            float4 bv = *(const float4*)&Bs[kk][tx * 4];
#pragma unroll
            for (int r = 0; r < RPT; r++) {
                float a = As[kk][ty * RPT + r];
                acc[r][0] = fmaf(a, bv.x, acc[r][0]);
                acc[r][1] = fmaf(a, bv.y, acc[r][1]);
                acc[r][2] = fmaf(a, bv.z, acc[r][2]);
                acc[r][3] = fmaf(a, bv.w, acc[r][3]);
            }
        }
        __syncthreads();
    }
    float4 asv = *(const float4*)&att_src[tx * 4];
    float4 adv = *(const float4*)&att_dst[tx * 4];
#pragma unroll
    for (int r = 0; r < RPT; r++) {
        int gr = row0 + ty * RPT + r;
        bool ok = gr < M;
        if (ok) {
            __half2 p0 = __floats2half2_rn(acc[r][0], acc[r][1]);
            __half2 p1 = __floats2half2_rn(acc[r][2], acc[r][3]);
            uint2 pk;
            pk.x = *(unsigned int*)&p0;
            pk.y = *(unsigned int*)&p1;
            *(uint2*)&g_h1h[gr * 128 + tx * 4] = pk;
        }
        float ps = acc[r][0] * asv.x + acc[r][1] * asv.y + acc[r][2] * asv.z + acc[r][3] * asv.w;
        float pd = acc[r][0] * adv.x + acc[r][1] * adv.y + acc[r][2] * adv.z + acc[r][3] * adv.w;
#pragma unroll
        for (int off = 1; off < 16; off <<= 1) {   // reduce within 16-lane halves (per head)
            ps += __shfl_xor_sync(0xffffffffu, ps, off);
            pd += __shfl_xor_sync(0xffffffffu, pd, off);
        }
        if ((tx & 15) == 0 && ok) {
            g_asrc1[gr * 2 + (tx >> 4)] = ps;
            g_adst1[gr * 2 + (tx >> 4)] = pd;
        }
    }
}

// ---------------- layer-1 softmax + aggregation + bias + ELU -----------------
__global__ void agg1_kernel(const float* __restrict__ b1, int N) {
    int gid = blockIdx.x * blockDim.x + threadIdx.x;
    int n = gid >> 5, lane = gid & 31;
    if (n >= N) return;
    int start = g_row[n], end = g_row[n + 1];
    int cb = lane * 4;
    bool head1 = lane >= 16;

    // denominators: lane-strided coalesced sweep over precomputed weights
    float s0 = 0.f, s1 = 0.f;
    for (int i = start + lane; i < end; i += 32) {
        float4 e = g_e1[i];
        s0 += e.x; s1 += e.y;
    }
#pragma unroll
    for (int off = 16; off; off >>= 1) {
        s0 += __shfl_xor_sync(0xffffffffu, s0, off);
        s1 += __shfl_xor_sync(0xffffffffu, s1, off);
    }

    // accumulation: all lanes walk the edge list (uniform loads, L1-hot)
    float a0 = 0.f, a1 = 0.f, a2 = 0.f, a3 = 0.f;
    int i = start;
    for (; i + 3 < end; i += 4) {
#pragma unroll
        for (int j = 0; j < 4; j++) {
            float4 e = g_e1[i + j];
            int s = __float_as_int(e.z);
            float w = head1 ? e.y : e.x;
            uint2 raw = *(const uint2*)&g_h1h[s * 128 + cb];
            float2 f0 = __half22float2(*(__half2*)&raw.x);
            float2 f1 = __half22float2(*(__half2*)&raw.y);
            a0 = fmaf(w, f0.x, a0);
            a1 = fmaf(w, f0.y, a1);
            a2 = fmaf(w, f1.x, a2);
            a3 = fmaf(w, f1.y, a3);
        }
    }
    for (; i < end; i++) {
        float4 e = g_e1[i];
        int s = __float_as_int(e.z);
        float w = head1 ? e.y : e.x;
        uint2 raw = *(const uint2*)&g_h1h[s * 128 + cb];
        float2 f0 = __half22float2(*(__half2*)&raw.x);
        float2 f1 = __half22float2(*(__half2*)&raw.y);
        a0 = fmaf(w, f0.x, a0);
        a1 = fmaf(w, f0.y, a1);
        a2 = fmaf(w, f1.x, a2);
        a3 = fmaf(w, f1.y, a3);
    }
    float inv = 1.f / ((head1 ? s1 : s0) + 1e-16f);
    float4 bb = *(const float4*)&b1[cb];
    float o0 = a0 * inv + bb.x; o0 = o0 > 0.f ? o0 : __expf(o0) - 1.f;
    float o1 = a1 * inv + bb.y; o1 = o1 > 0.f ? o1 : __expf(o1) - 1.f;
    float o2 = a2 * inv + bb.z; o2 = o2 > 0.f ? o2 : __expf(o2) - 1.f;
    float o3 = a3 * inv + bb.w; o3 = o3 > 0.f ? o3 : __expf(o3) - 1.f;
    *(float4*)&g_h2[n * 128 + cb] = make_float4(o0, o1, o2, o3);
}

// ------- fused mu+lv GEMM: g_hmlh = half(h2 @ [Wmu | Wlv]) + dots ------------
__global__ void gemm_mulv_kernel(const float* __restrict__ Bmu, const float* __restrict__ Blv,
                                 const float* __restrict__ asmu, const float* __restrict__ admu,
                                 const float* __restrict__ aslv, const float* __restrict__ adlv,
                                 int M) {
    constexpr int BM = 64, BK = 32, BN = 64;
    constexpr int TX = 16, TY = 16, RPT = 4;
    __shared__ float As[BK][BM + 1];
    __shared__ float Bs[BK][BN];
    int t = threadIdx.x;
    int tx = t % TX, ty = t / TX;
    int row0 = blockIdx.x * BM;
    float acc[RPT][4];
#pragma unroll
    for (int r = 0; r < RPT; r++) { acc[r][0] = acc[r][1] = acc[r][2] = acc[r][3] = 0.f; }

    for (int k0 = 0; k0 < 128; k0 += BK) {
        for (int i = t; i < BM * BK; i += 256) {
            int r = i / BK, kk = i % BK;
            int gr = row0 + r;
            As[kk][r] = (gr < M) ? g_h2[gr * 128 + k0 + kk] : 0.f;
        }
        for (int i = t; i < BK * BN; i += 256) {
            int kk = i / BN, c = i % BN;
            Bs[kk][c] = (c < 32) ? Bmu[(k0 + kk) * 32 + c] : Blv[(k0 + kk) * 32 + (c - 32)];
        }
        __syncthreads();
#pragma unroll
        for (int kk = 0; kk < BK; kk++) {
            float4 bv = *(const float4*)&Bs[kk][tx * 4];
#pragma unroll
            for (int r = 0; r < RPT; r++) {
                float a = As[kk][ty * RPT + r];
                acc[r][0] = fmaf(a, bv.x, acc[r][0]);
                acc[r][1] = fmaf(a, bv.y, acc[r][1]);
                acc[r][2] = fmaf(a, bv.z, acc[r][2]);
                acc[r][3] = fmaf(a, bv.w, acc[r][3]);
            }
        }
        __syncthreads();
    }
    bool islv = tx >= 8;
    int c0 = (tx * 4) & 31;   // channel base within the 32-dim latent
    float4 asv = islv ? *(const float4*)&aslv[c0] : *(const float4*)&asmu[c0];
    float4 adv = islv ? *(const float4*)&adlv[c0] : *(const float4*)&admu[c0];
#pragma unroll
    for (int r = 0; r < RPT; r++) {
        int gr = row0 + ty * RPT + r;
        bool ok = gr < M;
        if (ok) {
            // interleaved: mu channel c -> [gr*64 + 2c], lv channel c -> [gr*64 + 2c+1]
            g_hmlh[gr * 64 + 2 * (c0 + 0) + islv] = __float2half_rn(acc[r][0]);
            g_hmlh[gr * 64 + 2 * (c0 + 1) + islv] = __float2half_rn(acc[r][1]);
            g_hmlh[gr * 64 + 2 * (c0 + 2) + islv] = __float2half_rn(acc[r][2]);
            g_hmlh[gr * 64 + 2 * (c0 + 3) + islv] = __float2half_rn(acc[r][3]);
        }
        float ps = acc[r][0] * asv.x + acc[r][1] * asv.y + acc[r][2] * asv.z + acc[r][3] * asv.w;
        float pd = acc[r][0] * adv.x + acc[r][1] * adv.y + acc[r][2] * adv.z + acc[r][3] * adv.w;
#pragma unroll
        for (int off = 1; off < 8; off <<= 1) {    // reduce within 8-lane subgroup
            ps += __shfl_xor_sync(0xffffffffu, ps, off);
            pd += __shfl_xor_sync(0xffffffffu, pd, off);
        }
        float os = __shfl_xor_sync(0xffffffffu, ps, 8);  // grab the other net's sum
        float od = __shfl_xor_sync(0xffffffffu, pd, 8);
        if ((t & 15) == 0 && ok) {
            g_a2s[gr] = make_float2(ps, os);   // {mu, lv}
            g_a2d[gr] = make_float2(pd, od);
        }
    }
}

// ---------------- mu + lv softmax + aggregation (fused), writes output -------
__global__ void agg2_kernel(const float* __restrict__ bmu, const float* __restrict__ blv,
                            float* __restrict__ out, int N) {
    int gid = blockIdx.x * blockDim.x + threadIdx.x;
    int n = gid >> 5, lane = gid & 31;
    if (n >= N) return;
    int start = g_row[n], end = g_row[n + 1];

    float sm = 0.f, sl = 0.f;
    for (int i = start + lane; i < end; i += 32) {
        float4 e = g_e2[i];
        sm += e.x; sl += e.y;
    }
#pragma unroll
    for (int off = 16; off; off >>= 1) {
        sm += __shfl_xor_sync(0xffffffffu, sm, off);
        sl += __shfl_xor_sync(0xffffffffu, sl, off);
    }

    float accm = 0.f, accl = 0.f;
    int i = start;
    for (; i + 3 < end; i += 4) {
#pragma unroll
        for (int j = 0; j < 4; j++) {
            float4 e = g_e2[i + j];
            int s = __float_as_int(e.z);
            __half2 hv = *(const __half2*)&g_hmlh[s * 64 + lane * 2];  // {mu_c, lv_c}
            float2 f = __half22float2(hv);
            accm = fmaf(e.x, f.x, accm);
            accl = fmaf(e.y, f.y, accl);
        }
    }
    for (; i < end; i++) {
        float4 e = g_e2[i];
        int s = __float_as_int(e.z);
        __half2 hv = *(const __half2*)&g_hmlh[s * 64 + lane * 2];
        float2 f = __half22float2(hv);
        accm = fmaf(e.x, f.x, accm);
        accl = fmaf(e.y, f.y, accl);
    }
    out[n * 32 + lane]          = accm / (sm + 1e-16f) + bmu[lane];
    out[N * 32 + n * 32 + lane] = accl / (sl + 1e-16f) + blv[lane];
}

// ---------------- launch -----------------------------------------------------
extern "C" void kernel_launch(void* const* d_in, const int* in_sizes, int n_in,
                              void* d_out, int out_size) {
    const float* x          = (const float*)d_in[0];
    const int*   ei         = (const int*)d_in[1];
    const float* W1         = (const float*)d_in[2];
    const float* att_src1   = (const float*)d_in[3];
    const float* att_dst1   = (const float*)d_in[4];
    const float* b1         = (const float*)d_in[5];
    const float* Wmu        = (const float*)d_in[6];
    const float* att_src_mu = (const float*)d_in[7];
    const float* att_dst_mu = (const float*)d_in[8];
    const float* bmu        = (const float*)d_in[9];
    const float* Wlv        = (const float*)d_in[10];
    const float* att_src_lv = (const float*)d_in[11];
    const float* att_dst_lv = (const float*)d_in[12];
    const float* blv        = (const float*)d_in[13];
    float* out = (float*)d_out;

    int N = in_sizes[0] / 128;
    int E = in_sizes[1] / 2;
    int ET = E + N;
    int NB = (N + SCAN_CHUNK - 1) / SCAN_CHUNK;

    const int TB = 256;
    int warpBlocks = (N * 32 + TB - 1) / TB;
    int edgeBlocks = (ET + TB - 1) / TB;

    // lazily created once (on the uncaptured correctness call); reused in capture
    static cudaStream_t s1 = nullptr;
    static cudaEvent_t evFork = nullptr, evJoin = nullptr;
    if (s1 == nullptr) {
        cudaStreamCreateWithFlags(&s1, cudaStreamNonBlocking);
        cudaEventCreateWithFlags(&evFork, cudaEventDisableTiming);
        cudaEventCreateWithFlags(&evJoin, cudaEventDisableTiming);
    }

    // fork: CSR build on s1, gemm1 on the main stream, join before weight1
    cudaEventRecord(evFork, 0);
    cudaStreamWaitEvent(s1, evFork, 0);

    zero_counts_kernel<<<(N + TB - 1) / TB, TB, 0, s1>>>(N);
    hist_kernel<<<edgeBlocks, TB, 0, s1>>>(ei, E, N);
    block_sum_kernel<<<NB, 1024, 0, s1>>>(N);
    final_scan_kernel<<<NB, 1024, 0, s1>>>(N, NB, ET);
    scatter_kernel<<<edgeBlocks, TB, 0, s1>>>(ei, E, N);

    gemm1_kernel<<<(N + 63) / 64, TB>>>(x, W1, att_src1, att_dst1, N);

    cudaEventRecord(evJoin, s1);
    cudaStreamWaitEvent(0, evJoin, 0);

    // layer 1: per-edge weights, then lean aggregation
    weight1_kernel<<<edgeBlocks, TB>>>(ET);
    agg1_kernel<<<warpBlocks, TB>>>(b1, N);

    // mu + logvar: fused projection GEMM (+dots), weights, fused aggregation
    gemm_mulv_kernel<<<(N + 63) / 64, TB>>>(Wmu, Wlv, att_src_mu, att_dst_mu,
                                            att_src_lv, att_dst_lv, N);
    weight2_kernel<<<edgeBlocks, TB>>>(ET);
    agg2_kernel<<<warpBlocks, TB>>>(bmu, blv, out, N);
}